// round 9
// baseline (speedup 1.0000x reference)
#include <cuda_runtime.h>
#include <cstdint>

// Problem geometry
#define CB_K 512
#define CB_C 64
#define HW   4096                     // 64*64 pixels per (b,t) plane
#define NPLANES 128                   // B*T
#define N_PIX  (NPLANES * HW)         // 524288
#define Q_ELEMS (N_PIX * CB_C)        // 33554432
#define OFF_IDX  Q_ELEMS
#define OFF_LOSS (OFF_IDX + N_PIX)
#define OFF_ENT  (OFF_LOSS + 1)

// Kernel config: 512 threads, 1 pixel/thread, kt=8 (low register pressure, no spills)
#define THREADS 512
#define PIX_PER_CTA 512
#define NBLOCKS (N_PIX / PIX_PER_CTA) // 1024
#define ESTRIDE 516                   // padded floats per channel row of codebook
#define SMEM_FLOATS (CB_C * ESTRIDE)  // 33024 floats
#define SMEM_BYTES (SMEM_FLOATS*4 + CB_K*4 /*E*/ + CB_K*4 /*hist*/ + 4*4 /*lane_sum*/)

typedef unsigned long long u64;

__device__ double g_lane[4];          // per-(index mod 4) loss lane sums (XLA vec4 emulation)
__device__ int    g_counts[CB_K];

__global__ void vq_zero() {
    int t = threadIdx.x;
    if (t < CB_K) g_counts[t] = 0;
    if (t < 4)    g_lane[t] = 0.0;
}

__global__ void __launch_bounds__(THREADS, 1)
vq_main(const float* __restrict__ x, const float* __restrict__ cb, float* __restrict__ out) {
    extern __shared__ float smem[];
    float* es   = smem;                       // codebook transposed [c][k], padded stride 516
    float* ee   = smem + SMEM_FLOATS;         // E_k = sum_c e_{k,c}^2 (fp32 sequential fma)
    int*   hist = (int*)(ee + CB_K);          // per-CTA histogram
    float* lane_sum = (float*)(hist + CB_K);  // per-CTA loss partials, by (index mod 4)

    const int tid = threadIdx.x;

    // Stage codebook transposed (coalesced reads)
    for (int i = tid; i < CB_K * CB_C; i += THREADS) {
        int k = i >> 6, c = i & 63;
        es[c * ESTRIDE + k] = cb[i];
    }
    for (int k = tid; k < CB_K; k += THREADS) hist[k] = 0;
    if (tid < 4) lane_sum[tid] = 0.f;
    __syncthreads();
    // E_k = sum_c e^2, sequential fma ascending c (reference chain)
    for (int k = tid; k < CB_K; k += THREADS) {
        float s = 0.f;
        #pragma unroll
        for (int c = 0; c < CB_C; ++c) { float e = es[c * ESTRIDE + k]; s = __fmaf_rn(e, e, s); }
        ee[k] = s;
    }
    __syncthreads();

    // One pixel per thread; all 64 channels in registers (x read once, coalesced).
    const int plane = blockIdx.x >> 3;
    const int j = ((blockIdx.x & 7) * PIX_PER_CTA) + tid;
    const float* xp = x + (size_t)plane * (CB_C * HW) + j;

    float f[CB_C];
    #pragma unroll
    for (int c = 0; c < CB_C; ++c) f[c] = xp[(size_t)c * HW];

    // S = sum_c f_c^2, sequential fma ascending c
    float S = 0.f;
    #pragma unroll
    for (int c = 0; c < CB_C; ++c) S = __fmaf_rn(f[c], f[c], S);

    unsigned sbase = (unsigned)__cvta_generic_to_shared(es);
    unsigned hbase = (unsigned)__cvta_generic_to_shared(ee);

    float best = 3.4e38f;
    int bi = 0;

    // 64 tiles of 8 codes. Raw dot D in packed f32x2 (each lane = sequential fp32
    // fma over ascending c), then the reference two-rounding chain:
    //   t = fl(S - 2*D); d = fl(t + E_k); argmin ascending k, strict <.
    #pragma unroll 1
    for (int kt = 0; kt < CB_K / 8; ++kt) {
        u64 a0 = 0, a1 = 0, a2 = 0, a3 = 0;
        unsigned ebase = sbase + (unsigned)(kt * 32);
        #pragma unroll
        for (int c = 0; c < CB_C; ++c) {
            u64 e0, e1, e2, e3;
            unsigned ea = ebase + (unsigned)(c * (ESTRIDE * 4));
            asm volatile("ld.shared.v2.u64 {%0,%1}, [%2];"    : "=l"(e0), "=l"(e1) : "r"(ea));
            asm volatile("ld.shared.v2.u64 {%0,%1}, [%2+16];" : "=l"(e2), "=l"(e3) : "r"(ea));
            u64 fd;
            asm("mov.b64 %0, {%1,%1};" : "=l"(fd) : "f"(f[c]));
            asm("fma.rn.f32x2 %0, %1, %2, %0;" : "+l"(a0) : "l"(fd), "l"(e0));
            asm("fma.rn.f32x2 %0, %1, %2, %0;" : "+l"(a1) : "l"(fd), "l"(e1));
            asm("fma.rn.f32x2 %0, %1, %2, %0;" : "+l"(a2) : "l"(fd), "l"(e2));
            asm("fma.rn.f32x2 %0, %1, %2, %0;" : "+l"(a3) : "l"(fd), "l"(e3));
        }
        // Epilogue: E for these 8 codes, two reference roundings, streaming argmin.
        u64 h0, h1, h2, h3;
        {
            unsigned ha = hbase + (unsigned)(kt * 32);
            asm volatile("ld.shared.v2.u64 {%0,%1}, [%2];"    : "=l"(h0), "=l"(h1) : "r"(ha));
            asm volatile("ld.shared.v2.u64 {%0,%1}, [%2+16];" : "=l"(h2), "=l"(h3) : "r"(ha));
        }
        u64 av[4] = {a0, a1, a2, a3};
        u64 hv[4] = {h0, h1, h2, h3};
        #pragma unroll
        for (int q = 0; q < 4; ++q) {
            float elo = __uint_as_float((unsigned)hv[q]);
            float ehi = __uint_as_float((unsigned)(hv[q] >> 32));
            float Dlo = __uint_as_float((unsigned)av[q]);
            float Dhi = __uint_as_float((unsigned)(av[q] >> 32));
            float dlo = __fadd_rn(__fmaf_rn(-2.f, Dlo, S), elo);
            float dhi = __fadd_rn(__fmaf_rn(-2.f, Dhi, S), ehi);
            int k0 = kt * 8 + 2 * q;
            if (dlo < best) { best = dlo; bi = k0;     }
            if (dhi < best) { best = dhi; bi = k0 + 1; }
        }
    }

    // Histogram (shared)
    atomicAdd(&hist[bi], 1);

    // ---- Loss: XLA CPU single-NEON-vec4 fp32 reduction emulation (validated R3) ----
    const bool quant = (plane >= 2);
    float scaleQ = 1.f, invQ = 1.f;
    if (quant) {
        int lg = 31 - __clz(plane);          // 1..6
        int kq = 7 - lg;                     // 6..1
        scaleQ = (float)(1 << kq);
        invQ   = 1.f / (float)(1 << kq);
    }

    float acc = 0.f;
    float* outq = out + (size_t)plane * (CB_C * HW) + j;
    #pragma unroll
    for (int c = 0; c < CB_C; ++c) {
        float q  = es[c * ESTRIDE + bi];
        float da = __fsub_rn(q, f[c]);
        float v  = __fmul_rn(da, da);
        if (quant) {
            float mm = __fsub_rn(__fmaf_rn(v, scaleQ, 8388608.f), 8388608.f); // rtn_even(v*2^k)
            acc = __fmaf_rn(mm, invQ, acc);   // exact: multiples of u
        } else {
            acc = __fadd_rn(v, acc);
        }
        outq[(size_t)c * HW] = __fadd_rn(f[c], da);   // quantized_st = fl(x + fl(q-x))
    }
    out[OFF_IDX + (size_t)plane * HW + j] = (float)bi;

    // CTA-level per-lane reduce (fp32 shared atomics exact: multiples of u, bounded),
    // then one double atomic per lane per CTA.
    atomicAdd(&lane_sum[j & 3], acc);
    __syncthreads();
    if (tid < 4) atomicAdd(&g_lane[tid], (double)lane_sum[tid]);

    // Histogram flush
    for (int k = tid; k < CB_K; k += THREADS) {
        int cth = hist[k];
        if (cth) atomicAdd(&g_counts[k], cth);
    }
}

__global__ void vq_finalize(float* __restrict__ out) {
    __shared__ double red[CB_K];
    int t = threadIdx.x;
    int c = g_counts[t];
    double p = (double)c / (double)N_PIX;
    red[t] = (c > 0) ? (-p * log2(p)) : 0.0;
    __syncthreads();
    for (int o = CB_K / 2; o > 0; o >>= 1) {
        if (t < o) red[t] += red[t + o];
        __syncthreads();
    }
    if (t == 0) {
        out[OFF_ENT] = (float)red[0];
        // NEON faddp horizontal reduce: (s0+s1) + (s2+s3), all fp32.
        float s0 = (float)g_lane[0], s1 = (float)g_lane[1];
        float s2 = (float)g_lane[2], s3 = (float)g_lane[3];
        float hs = __fadd_rn(__fadd_rn(s0, s1), __fadd_rn(s2, s3));
        float L  = hs * (1.f / 33554432.f);        // exact power-of-2 scale
        out[OFF_LOSS] = __fadd_rn(L, 0.25f * L);   // vq = L + 0.25*L
    }
}

extern "C" void kernel_launch(void* const* d_in, const int* in_sizes, int n_in,
                              void* d_out, int out_size) {
    const float* x  = (const float*)d_in[0];
    const float* cb = (const float*)d_in[1];
    float* out = (float*)d_out;
    cudaFuncSetAttribute(vq_main, cudaFuncAttributeMaxDynamicSharedMemorySize, SMEM_BYTES);
    vq_zero<<<1, CB_K>>>();
    vq_main<<<NBLOCKS, THREADS, SMEM_BYTES>>>(x, cb, out);
    vq_finalize<<<1, CB_K>>>(out);
}